// round 2
// baseline (speedup 1.0000x reference)
#include <cuda_runtime.h>
#include <stdint.h>

// out[bc, morton(i,j)] = x[bc, i, j]
// morton: even bits <- j (cols), odd bits <- i (rows).
// For output index m: j = compact_even_bits(m), i = compact_odd_bits(m).
//
// Each thread handles 16 consecutive output elements (m 16-aligned), which map
// to a 4x4 tile of x rooted at (i, j) with i, j both 4-aligned:
//   m + 0..3   -> rows i+0..1, cols j+0..1   (2x2 sub-tile)
//   m + 4..7   -> rows i+0..1, cols j+2..3
//   m + 8..11  -> rows i+2..3, cols j+0..1
//   m + 12..15 -> rows i+2..3, cols j+2..3
// Row r of the 4x4 tile (float4 load, 16B aligned) scatters into the four
// output float4s in a fixed pattern. We load 4x float4, shuffle in registers,
// store 4x float4 (64B contiguous per thread).

__global__ void __launch_bounds__(256) morton_gather_kernel(
    const float* __restrict__ x, float* __restrict__ out)
{
    unsigned tid = blockIdx.x * blockDim.x + threadIdx.x;
    unsigned p  = tid << 4;          // global output index (16 per thread)
    unsigned bc = p >> 16;           // (B,C) plane (65536 elems each)
    unsigned m  = p & 0xFFFFu;       // morton index within plane (16-aligned)

    // deinterleave: even bits -> j, odd bits -> i (low 2 bits of each are 0)
    unsigned e = m & 0x5555u;
    e = (e | (e >> 1)) & 0x3333u;
    e = (e | (e >> 2)) & 0x0F0Fu;
    e = (e | (e >> 4)) & 0x00FFu;    // j, 4-aligned

    unsigned o = (m >> 1) & 0x5555u;
    o = (o | (o >> 1)) & 0x3333u;
    o = (o | (o >> 2)) & 0x0F0Fu;
    o = (o | (o >> 4)) & 0x00FFu;    // i, 4-aligned

    const float4* base = reinterpret_cast<const float4*>(
        x + ((size_t)bc << 16) + (o << 8) + e);
    // rows of the 4x4 tile; stride between rows = 256 floats = 64 float4
    float4 r0 = base[0];
    float4 r1 = base[64];
    float4 r2 = base[128];
    float4 r3 = base[192];

    float4* dst = reinterpret_cast<float4*>(out + p);
    // m+0..3  = r0.x r0.y r1.x r1.y
    dst[0] = make_float4(r0.x, r0.y, r1.x, r1.y);
    // m+4..7  = r0.z r0.w r1.z r1.w
    dst[1] = make_float4(r0.z, r0.w, r1.z, r1.w);
    // m+8..11 = r2.x r2.y r3.x r3.y
    dst[2] = make_float4(r2.x, r2.y, r3.x, r3.y);
    // m+12..15= r2.z r2.w r3.z r3.w
    dst[3] = make_float4(r2.z, r2.w, r3.z, r3.w);
}

extern "C" void kernel_launch(void* const* d_in, const int* in_sizes, int n_in,
                              void* d_out, int out_size)
{
    const float* x = (const float*)d_in[0];
    float* out = (float*)d_out;
    // out_size = 8*64*256*256 = 33,554,432 elements; 16 per thread
    int total_threads = out_size >> 4;          // 2,097,152
    int block = 256;
    int grid = (total_threads + block - 1) / block;  // 8192
    morton_gather_kernel<<<grid, block>>>(x, out);
}

// round 4
// speedup vs baseline: 1.0110x; 1.0110x over previous
#include <cuda_runtime.h>
#include <stdint.h>

// out[bc, morton(i,j)] = x[bc, i, j]
// 16 outputs per thread = one 4x4 tile of x -> 4x LDG.128 + 4x STG.128.
//
// Cache policy: x (134MB) nearly fits in L2 (~126MB) and is re-read on every
// graph replay; out is write-once streaming. sm_100a ptxas rejects inline
// evict modifiers on 128-bit accesses, so use createpolicy + L2::cache_hint:
//   loads of x  -> evict_last  (keep resident in L2)
//   stores of out -> evict_first (don't pollute / evict x)

__device__ __forceinline__ uint64_t make_policy_evict_last() {
    uint64_t pol;
    asm("createpolicy.fractional.L2::evict_last.b64 %0, 1.0;" : "=l"(pol));
    return pol;
}

__device__ __forceinline__ uint64_t make_policy_evict_first() {
    uint64_t pol;
    asm("createpolicy.fractional.L2::evict_first.b64 %0, 1.0;" : "=l"(pol));
    return pol;
}

__device__ __forceinline__ float4 ldg_hint(const float4* p, uint64_t pol) {
    float4 v;
    asm volatile("ld.global.nc.L2::cache_hint.v4.f32 {%0,%1,%2,%3}, [%4], %5;"
                 : "=f"(v.x), "=f"(v.y), "=f"(v.z), "=f"(v.w)
                 : "l"(p), "l"(pol));
    return v;
}

__device__ __forceinline__ void stg_hint(float4* p, float4 v, uint64_t pol) {
    asm volatile("st.global.L2::cache_hint.v4.f32 [%0], {%1,%2,%3,%4}, %5;"
                 :: "l"(p), "f"(v.x), "f"(v.y), "f"(v.z), "f"(v.w), "l"(pol)
                 : "memory");
}

__global__ void __launch_bounds__(256) morton_gather_kernel(
    const float* __restrict__ x, float* __restrict__ out)
{
    unsigned tid = blockIdx.x * blockDim.x + threadIdx.x;
    unsigned p  = tid << 4;          // global output index (16 per thread)
    unsigned bc = p >> 16;           // (B,C) plane (65536 elems each)
    unsigned m  = p & 0xFFFFu;       // morton index within plane (16-aligned)

    // deinterleave: even bits -> j, odd bits -> i (low 2 bits of each are 0)
    unsigned e = m & 0x5555u;
    e = (e | (e >> 1)) & 0x3333u;
    e = (e | (e >> 2)) & 0x0F0Fu;
    e = (e | (e >> 4)) & 0x00FFu;    // j, 4-aligned

    unsigned o = (m >> 1) & 0x5555u;
    o = (o | (o >> 1)) & 0x3333u;
    o = (o | (o >> 2)) & 0x0F0Fu;
    o = (o | (o >> 4)) & 0x00FFu;    // i, 4-aligned

    uint64_t pol_keep   = make_policy_evict_last();
    uint64_t pol_stream = make_policy_evict_first();

    const float4* base = reinterpret_cast<const float4*>(
        x + ((size_t)bc << 16) + (o << 8) + e);
    // rows of the 4x4 tile; stride between rows = 256 floats = 64 float4
    float4 r0 = ldg_hint(base,       pol_keep);
    float4 r1 = ldg_hint(base + 64,  pol_keep);
    float4 r2 = ldg_hint(base + 128, pol_keep);
    float4 r3 = ldg_hint(base + 192, pol_keep);

    float4* dst = reinterpret_cast<float4*>(out + p);
    stg_hint(dst + 0, make_float4(r0.x, r0.y, r1.x, r1.y), pol_stream);
    stg_hint(dst + 1, make_float4(r0.z, r0.w, r1.z, r1.w), pol_stream);
    stg_hint(dst + 2, make_float4(r2.x, r2.y, r3.x, r3.y), pol_stream);
    stg_hint(dst + 3, make_float4(r2.z, r2.w, r3.z, r3.w), pol_stream);
}

extern "C" void kernel_launch(void* const* d_in, const int* in_sizes, int n_in,
                              void* d_out, int out_size)
{
    const float* x = (const float*)d_in[0];
    float* out = (float*)d_out;
    int total_threads = out_size >> 4;          // 2,097,152
    int block = 256;
    int grid = (total_threads + block - 1) / block;  // 8192
    morton_gather_kernel<<<grid, block>>>(x, out);
}